// round 3
// baseline (speedup 1.0000x reference)
#include <cuda_runtime.h>
#include <cuda_bf16.h>
#include <cstdint>

// Problem dims
#define B_  32
#define I_  128
#define O_  256
#define E_  8
#define HW_ 3136   // 56*56
#define HH_ 56
#define WW_ 56
#define HID_ 32
#define PER_EXPERT (O_*I_*9)   // 294912

// Scratch (allocation-free: __device__ globals)
__device__ float g_r[B_*E_];
__device__ float g_cb[B_*O_];
__device__ float g_cw[(size_t)B_*O_*I_*9];   // 37.75 MB

// ---------------------------------------------------------------------------
// Kernel 1: routing. One block per sample, 256 threads.
// pooled = mean(x, HW); h = relu(pooled@w1^T+b1); r = softmax(h@w2^T+b2)
// cb = r @ bias
// ---------------------------------------------------------------------------
__global__ __launch_bounds__(256) void routing_kernel(
    const float* __restrict__ x, const float* __restrict__ bias,
    const float* __restrict__ w1, const float* __restrict__ b1,
    const float* __restrict__ w2, const float* __restrict__ b2)
{
    int b = blockIdx.x;
    __shared__ float s_pool[I_];
    __shared__ float s_h[HID_];
    __shared__ float s_logit[E_];
    __shared__ float s_r[E_];

    int t = threadIdx.x, lane = t & 31, warp = t >> 5;
    const float* xb = x + (size_t)b * I_ * HW_;

    // per-channel mean: one warp per channel (8 warps, 16 channels each)
    for (int c = warp; c < I_; c += 8) {
        const float* xc = xb + (size_t)c * HW_;
        float s = 0.f;
        for (int i = lane; i < HW_; i += 32) s += xc[i];
        #pragma unroll
        for (int o = 16; o; o >>= 1) s += __shfl_xor_sync(0xffffffffu, s, o);
        if (lane == 0) s_pool[c] = s * (1.0f / (float)HW_);
    }
    __syncthreads();

    if (t < HID_) {
        float s = b1[t];
        #pragma unroll 8
        for (int i = 0; i < I_; i++) s += s_pool[i] * w1[t * I_ + i];
        s_h[t] = fmaxf(s, 0.f);
    }
    __syncthreads();

    if (t < E_) {
        float s = b2[t];
        #pragma unroll
        for (int j = 0; j < HID_; j++) s += s_h[j] * w2[t * HID_ + j];
        s_logit[t] = s;
    }
    __syncthreads();

    if (t < E_) {
        float m = s_logit[0];
        #pragma unroll
        for (int e = 1; e < E_; e++) m = fmaxf(m, s_logit[e]);
        float den = 0.f;
        #pragma unroll
        for (int e = 0; e < E_; e++) den += expf(s_logit[e] - m);
        float rv = expf(s_logit[t] - m) / den;
        s_r[t] = rv;
        g_r[b * E_ + t] = rv;
    }
    __syncthreads();

    if (t < O_) {
        float s = 0.f;
        #pragma unroll
        for (int e = 0; e < E_; e++) s += s_r[e] * bias[e * O_ + t];
        g_cb[b * O_ + t] = s;
    }
}

// ---------------------------------------------------------------------------
// Kernel 2: combine per-sample weights  cw[b,*] = sum_e r[b,e] * W[e,*]
// ---------------------------------------------------------------------------
__global__ __launch_bounds__(256) void combine_kernel(const float* __restrict__ weight)
{
    size_t idx = (size_t)blockIdx.x * 256 + threadIdx.x;
    int b = (int)(idx / PER_EXPERT);
    size_t rest = idx % PER_EXPERT;
    float r0 = g_r[b * E_ + 0], r1 = g_r[b * E_ + 1];
    float r2 = g_r[b * E_ + 2], r3 = g_r[b * E_ + 3];
    float r4 = g_r[b * E_ + 4], r5 = g_r[b * E_ + 5];
    float r6 = g_r[b * E_ + 6], r7 = g_r[b * E_ + 7];
    float s = r0 * weight[0 * (size_t)PER_EXPERT + rest]
            + r1 * weight[1 * (size_t)PER_EXPERT + rest]
            + r2 * weight[2 * (size_t)PER_EXPERT + rest]
            + r3 * weight[3 * (size_t)PER_EXPERT + rest]
            + r4 * weight[4 * (size_t)PER_EXPERT + rest]
            + r5 * weight[5 * (size_t)PER_EXPERT + rest]
            + r6 * weight[6 * (size_t)PER_EXPERT + rest]
            + r7 * weight[7 * (size_t)PER_EXPERT + rest];
    g_cw[idx] = s;
}

// ---------------------------------------------------------------------------
// Kernel 3: direct 3x3 conv, per-sample weights.
// Block: (sample b, 64 out-channels, 4 rows x 56 cols). 256 threads.
// Thread: 8 oc x 7 cols = 56 accumulators.
// smem: x tile ICC x 6 x 58, w tile 64 x ICC x 9.
// ---------------------------------------------------------------------------
#define ICC 8
#define XROWS 6
#define XCOLS 58

__global__ __launch_bounds__(256) void conv_kernel(
    const float* __restrict__ x, float* __restrict__ out)
{
    int b   = blockIdx.z;
    int oc0 = blockIdx.y * 64;
    int r0  = blockIdx.x * 4;

    __shared__ float xs[ICC * XROWS * XCOLS];     // 11.1 KB
    __shared__ float ws[64 * ICC * 9];            // 18.4 KB

    int t    = threadIdx.x;
    int ocg  = t >> 5;          // 0..7  (uniform within warp -> broadcast w-LDS)
    int pix  = t & 31;
    int row  = pix >> 3;        // 0..3
    int col0 = (pix & 7) * 7;   // 0,7,...,49

    float acc[8][7];
    #pragma unroll
    for (int j = 0; j < 8; j++)
        #pragma unroll
        for (int p = 0; p < 7; p++) acc[j][p] = 0.f;

    const float* xb  = x + (size_t)b * I_ * HW_;
    const float* cwb = g_cw + ((size_t)b * O_ + oc0) * (I_ * 9);

    for (int ic0 = 0; ic0 < I_; ic0 += ICC) {
        // stage x tile (with halo + zero padding)
        for (int idx = t; idx < ICC * XROWS * XCOLS; idx += 256) {
            int ic  = idx / (XROWS * XCOLS);
            int rem = idx % (XROWS * XCOLS);
            int rr  = rem / XCOLS;
            int cc  = rem % XCOLS;
            int gh  = r0 - 1 + rr;
            int gw  = cc - 1;
            float v = 0.f;
            if (gh >= 0 && gh < HH_ && gw >= 0 && gw < WW_)
                v = xb[(size_t)(ic0 + ic) * HW_ + gh * WW_ + gw];
            xs[idx] = v;
        }
        // stage weight tile: 64 oc x ICC ic x 9
        for (int idx = t; idx < 64 * ICC * 9; idx += 256) {
            int oc  = idx / (ICC * 9);
            int rem = idx % (ICC * 9);
            int ic  = rem / 9;
            int k   = rem % 9;
            ws[idx] = cwb[(size_t)oc * (I_ * 9) + (ic0 + ic) * 9 + k];
        }
        __syncthreads();

        #pragma unroll
        for (int ic = 0; ic < ICC; ic++) {
            #pragma unroll
            for (int kh = 0; kh < 3; kh++) {
                float xr[9];
                #pragma unroll
                for (int c = 0; c < 9; c++)
                    xr[c] = xs[ic * (XROWS * XCOLS) + (row + kh) * XCOLS + col0 + c];
                #pragma unroll
                for (int kw = 0; kw < 3; kw++) {
                    #pragma unroll
                    for (int j = 0; j < 8; j++) {
                        float wv = ws[(ocg * 8 + j) * (ICC * 9) + ic * 9 + kh * 3 + kw];
                        #pragma unroll
                        for (int p = 0; p < 7; p++)
                            acc[j][p] = fmaf(wv, xr[p + kw], acc[j][p]);
                    }
                }
            }
        }
        __syncthreads();
    }

    // epilogue: add per-sample bias, store
    int h = r0 + row;
    #pragma unroll
    for (int j = 0; j < 8; j++) {
        int oc = oc0 + ocg * 8 + j;
        float cb = g_cb[b * O_ + oc];
        float* op = out + ((size_t)b * O_ + oc) * HW_ + h * WW_ + col0;
        #pragma unroll
        for (int p = 0; p < 7; p++) op[p] = acc[j][p] + cb;
    }
}

// ---------------------------------------------------------------------------
extern "C" void kernel_launch(void* const* d_in, const int* in_sizes, int n_in,
                              void* d_out, int out_size)
{
    const float* x      = (const float*)d_in[0];
    const float* weight = (const float*)d_in[1];
    const float* bias   = (const float*)d_in[2];
    const float* w1     = (const float*)d_in[3];
    const float* b1     = (const float*)d_in[4];
    const float* w2     = (const float*)d_in[5];
    const float* b2     = (const float*)d_in[6];
    float* out = (float*)d_out;

    routing_kernel<<<B_, 256>>>(x, bias, w1, b1, w2, b2);

    size_t cw_total = (size_t)B_ * PER_EXPERT;           // 9,437,184
    combine_kernel<<<(unsigned)(cw_total / 256), 256>>>(weight);

    dim3 grid(HH_ / 4, O_ / 64, B_);                      // (14, 4, 32)
    conv_kernel<<<grid, 256>>>(x, out);
}